// round 3
// baseline (speedup 1.0000x reference)
#include <cuda_runtime.h>
#include <cstdint>

#define TLEN 2048
#define HEADS 8
#define HDIM 32
#define BSZ 4
#define NEMB 256

__device__ float g_Q[(size_t)BSZ*HEADS*TLEN*HDIM];
__device__ float g_K[(size_t)BSZ*HEADS*TLEN*HDIM];
__device__ float g_V[(size_t)BSZ*HEADS*TLEN*HDIM];
__device__ float g_O[(size_t)BSZ*TLEN*NEMB];

// ---------------------------------------------------------------------------
__device__ __forceinline__ uint32_t f2tf(float x) {
    uint32_t r;
    asm("cvt.rna.tf32.f32 %0, %1;" : "=r"(r) : "f"(x));
    return r;
}
__device__ __forceinline__ float tfbits(float x) {   // tf32-rounded value as float
    return __uint_as_float(f2tf(x));
}

__device__ __forceinline__ void mma_tf32(float c[4],
                                         uint32_t a0, uint32_t a1, uint32_t a2, uint32_t a3,
                                         uint32_t b0, uint32_t b1) {
    asm volatile(
        "mma.sync.aligned.m16n8k8.row.col.f32.tf32.tf32.f32 "
        "{%0,%1,%2,%3}, {%4,%5,%6,%7}, {%8,%9}, {%0,%1,%2,%3};\n"
        : "+f"(c[0]), "+f"(c[1]), "+f"(c[2]), "+f"(c[3])
        : "r"(a0), "r"(a1), "r"(a2), "r"(a3), "r"(b0), "r"(b1));
}

// ---------------------------------------------------------------------------
// Kernel 1: qkv = x @ w_attn, split K|Q|V, heads layout, fold 1/sqrt(32) in Q.
// ---------------------------------------------------------------------------
__global__ void qkv_kernel(const float* __restrict__ x, const float* __restrict__ w) {
    __shared__ float As[64][20];
    __shared__ float Bs[16][68];
    int tid = threadIdx.x;
    int tx = tid & 15, ty = tid >> 4;
    int m0 = blockIdx.y * 64, n0 = blockIdx.x * 64;

    float acc[4][4] = {};

    for (int kk = 0; kk < 256; kk += 16) {
        {
            int row = tid >> 2, c4 = (tid & 3) * 4;
            float4 v = *(const float4*)&x[(size_t)(m0 + row) * 256 + kk + c4];
            As[row][c4] = v.x; As[row][c4+1] = v.y; As[row][c4+2] = v.z; As[row][c4+3] = v.w;
        }
        {
            int r = tid >> 4, c4 = (tid & 15) * 4;
            float4 v = *(const float4*)&w[(size_t)(kk + r) * 768 + n0 + c4];
            Bs[r][c4] = v.x; Bs[r][c4+1] = v.y; Bs[r][c4+2] = v.z; Bs[r][c4+3] = v.w;
        }
        __syncthreads();
#pragma unroll
        for (int k = 0; k < 16; k++) {
            float4 bv = *(const float4*)&Bs[k][tx * 4];
            float a0 = As[ty*4+0][k], a1 = As[ty*4+1][k], a2 = As[ty*4+2][k], a3 = As[ty*4+3][k];
            acc[0][0] += a0*bv.x; acc[0][1] += a0*bv.y; acc[0][2] += a0*bv.z; acc[0][3] += a0*bv.w;
            acc[1][0] += a1*bv.x; acc[1][1] += a1*bv.y; acc[1][2] += a1*bv.z; acc[1][3] += a1*bv.w;
            acc[2][0] += a2*bv.x; acc[2][1] += a2*bv.y; acc[2][2] += a2*bv.z; acc[2][3] += a2*bv.w;
            acc[3][0] += a3*bv.x; acc[3][1] += a3*bv.y; acc[3][2] += a3*bv.z; acc[3][3] += a3*bv.w;
        }
        __syncthreads();
    }

    int c_base = n0 + tx * 4;
    int part = c_base >> 8;              // 0=K, 1=Q, 2=V
    int cc = c_base & 255;
    int h = cc >> 5, d = cc & 31;
    float scale = (part == 1) ? 0.17677669529663687f : 1.0f;
    float* dst = (part == 0) ? g_K : (part == 1) ? g_Q : g_V;
#pragma unroll
    for (int i = 0; i < 4; i++) {
        int m = m0 + ty * 4 + i;
        int b = m >> 11, t = m & 2047;
        float* p = &dst[(((size_t)(b * HEADS + h)) * TLEN + t) * HDIM + d];
#pragma unroll
        for (int j = 0; j < 4; j++) p[j] = acc[i][j] * scale;
    }
}

// ---------------------------------------------------------------------------
// Kernel 2: flash attention, tf32 mma, warp-owns-rows layout.
// BQ=128, BK=64, 8 warps (16 rows each, all 64 cols).
// S[i,j] = Q·K^T + R[i, j-i+127], R = Q·pe_band^T,
// pe band abs rows = gbase + u, u in [0,191], gbase = 1920 - t0 + s0.
// pe is a 192-row ring buffer keyed by abs_row % 192 (+64 rows per iter).
// Smem stores tf32 bit patterns; B-fragment pairs are LDS.64 via k-permute:
//   pos(k) = (k & ~7) + (k&3)*2 + ((k>>2)&1)
// ---------------------------------------------------------------------------
#define KS_STRIDE 40
#define VT_STRIDE 72
#define PE_STRIDE 40
#define SS_STRIDE 68

__global__ void __launch_bounds__(256, 2) attn_kernel(const float* __restrict__ pos) {
    extern __shared__ float sm[];
    float* Ks  = sm;                     // [64][40]   tf32 bits, k-permuted
    float* Vt  = Ks + 64 * KS_STRIDE;    // [32][72]   V^T, tf32 bits, k-permuted
    float* Pes = Vt + 32 * VT_STRIDE;    // [192][40]  ring, tf32 bits, k-permuted
    float* Ss  = Pes + 192 * PE_STRIDE;  // [128][68]  raw scores -> tf32(P)

    int tid = threadIdx.x;
    int lane = tid & 31, wid = tid >> 5;
    int g = lane >> 2, t4 = lane & 3;
    int h = blockIdx.y, b = blockIdx.z;
    int t0 = (gridDim.x - 1 - blockIdx.x) * 128;   // big tiles first

    const float* Kb  = &g_K[((size_t)(b * HEADS + h)) * TLEN * HDIM];
    const float* Vb  = &g_V[((size_t)(b * HEADS + h)) * TLEN * HDIM];
    const float* peh = &pos[(size_t)h * TLEN * HDIM];

    int r0l = wid * 16 + g;      // CTA-local rows owned by this lane's frags
    int r1l = r0l + 8;

    // --- Q A-fragments: load once from gmem, tf32, registers for whole CTA ---
    uint32_t qa[4][4];
    {
        const float* q0 = &g_Q[(((size_t)(b * HEADS + h)) * TLEN + t0 + r0l) * HDIM];
        const float* q1 = q0 + 8 * HDIM;
#pragma unroll
        for (int ks = 0; ks < 4; ks++) {
            qa[ks][0] = f2tf(q0[ks*8 + t4]);
            qa[ks][1] = f2tf(q1[ks*8 + t4]);
            qa[ks][2] = f2tf(q0[ks*8 + t4 + 4]);
            qa[ks][3] = f2tf(q1[ks*8 + t4 + 4]);
        }
    }

    float o[4][4] = {};                 // O frags: rows r0l/r1l, cols nt*8+2t4+{0,1}
    float m0s = -1e30f, l0s = 0.0f;
    float m1s = -1e30f, l1s = 0.0f;

    int nK = t0 / 64 + 2;
    for (int kt = 0; kt < nK; kt++) {
        int s0 = kt * 64;
        int gbase = 1920 - t0 + s0;
        __syncthreads();   // prior iter's reads of Ks/Vt/Pes done

        // ---- load K tile (64x32) ----
        for (int v = tid; v < 512; v += 256) {
            int row = v >> 3, d0 = (v & 7) * 4;
            float4 kv = *(const float4*)&Kb[(size_t)(s0 + row) * 32 + d0];
            int base = row * KS_STRIDE + (d0 & ~7);
            int half = (d0 >> 2) & 1;
            Ks[base + 0 + half] = tfbits(kv.x);
            Ks[base + 2 + half] = tfbits(kv.y);
            Ks[base + 4 + half] = tfbits(kv.z);
            Ks[base + 6 + half] = tfbits(kv.w);
        }
        // ---- load V tile transposed: Vt[d][k] ----
        for (int v = tid; v < 512; v += 256) {
            int row = v >> 3, d0 = (v & 7) * 4;   // row = k index
            float4 vv = *(const float4*)&Vb[(size_t)(s0 + row) * 32 + d0];
            int kpos = (row & ~7) + ((row & 3) << 1) + ((row >> 2) & 1);
            Vt[(d0+0) * VT_STRIDE + kpos] = tfbits(vv.x);
            Vt[(d0+1) * VT_STRIDE + kpos] = tfbits(vv.y);
            Vt[(d0+2) * VT_STRIDE + kpos] = tfbits(vv.z);
            Vt[(d0+3) * VT_STRIDE + kpos] = tfbits(vv.w);
        }
        // ---- load pe rows into ring (192 rows first iter, 64 after) ----
        {
            int start = (kt == 0) ? gbase : gbase + 128;
            int n4 = (kt == 0) ? 1536 : 512;
            for (int v = tid; v < n4; v += 256) {
                int u = v >> 3, d0 = (v & 7) * 4;
                int absr = start + u;
                int gr = absr > 2047 ? 2047 : absr;
                float4 p = *(const float4*)&peh[(size_t)gr * 32 + d0];
                int slot = absr % 192;
                int base = slot * PE_STRIDE + (d0 & ~7);
                int half = (d0 >> 2) & 1;
                Pes[base + 0 + half] = tfbits(p.x);
                Pes[base + 2 + half] = tfbits(p.y);
                Pes[base + 4 + half] = tfbits(p.z);
                Pes[base + 6 + half] = tfbits(p.w);
            }
        }
        __syncthreads();

        bool active = (t0 + wid * 16 + 15) >= s0;   // any unmasked row?
        if (active) {
            // ---- QK: S[16,64] for own rows ----
#pragma unroll
            for (int nt = 0; nt < 8; nt++) {
                float c[4] = {0,0,0,0};
                const float* kp = &Ks[(nt*8 + g) * KS_STRIDE + t4*2];
#pragma unroll
                for (int ks = 0; ks < 4; ks++) {
                    float2 bp = *(const float2*)(kp + ks*8);
                    mma_tf32(c, qa[ks][0], qa[ks][1], qa[ks][2], qa[ks][3],
                             __float_as_uint(bp.x), __float_as_uint(bp.y));
                }
                int col = nt*8 + 2*t4;
                Ss[r0l * SS_STRIDE + col]     = c[0];
                Ss[r0l * SS_STRIDE + col + 1] = c[1];
                Ss[r1l * SS_STRIDE + col]     = c[2];
                Ss[r1l * SS_STRIDE + col + 1] = c[3];
            }
            __syncwarp();

            // ---- band: R[16,192], scatter-add S[i][u+i-127] ----
            int bm = gbase % 192;
#pragma unroll
            for (int ut = 0; ut < 24; ut++) {
                int br = bm + ut*8 + g; if (br >= 192) br -= 192;
                float c[4] = {0,0,0,0};
                const float* pp = &Pes[br * PE_STRIDE + t4*2];
#pragma unroll
                for (int ks = 0; ks < 4; ks++) {
                    float2 bp = *(const float2*)(pp + ks*8);
                    mma_tf32(c, qa[ks][0], qa[ks][1], qa[ks][2], qa[ks][3],
                             __float_as_uint(bp.x), __float_as_uint(bp.y));
                }
                int u0 = ut*8 + 2*t4;
                int j0 = u0 + r0l - 127;
                if ((unsigned)j0     < 64u) Ss[r0l * SS_STRIDE + j0]     += c[0];
                if ((unsigned)(j0+1) < 64u) Ss[r0l * SS_STRIDE + j0 + 1] += c[1];
                int j1 = j0 + 8;
                if ((unsigned)j1     < 64u) Ss[r1l * SS_STRIDE + j1]     += c[2];
                if ((unsigned)(j1+1) < 64u) Ss[r1l * SS_STRIDE + j1 + 1] += c[3];
            }
            __syncwarp();

            // ---- online softmax, rows r0l and r1l (quad t4 0..3) ----
            float cf0, cf1;
            {
                int rb = r0l * SS_STRIDE;
                int tmax = t0 + r0l - s0;
                float mloc = -1e30f;
#pragma unroll
                for (int jj = 0; jj < 16; jj++) {
                    int cc = t4*16 + jj;
                    float v = Ss[rb + cc];
                    mloc = fmaxf(mloc, (cc <= tmax) ? v : -1e30f);
                }
                mloc = fmaxf(mloc, __shfl_xor_sync(0xffffffffu, mloc, 1));
                mloc = fmaxf(mloc, __shfl_xor_sync(0xffffffffu, mloc, 2));
                float mn = fmaxf(m0s, mloc);
                cf0 = __expf(m0s - mn);
                float ssum = 0.0f;
#pragma unroll
                for (int jj = 0; jj < 16; jj++) {
                    int cc = t4*16 + jj;
                    float v = Ss[rb + cc];
                    float e = (cc <= tmax) ? __expf(v - mn) : 0.0f;
                    Ss[rb + cc] = tfbits(e);
                    ssum += e;
                }
                ssum += __shfl_xor_sync(0xffffffffu, ssum, 1);
                ssum += __shfl_xor_sync(0xffffffffu, ssum, 2);
                l0s = l0s * cf0 + ssum;
                m0s = mn;
            }
            {
                int rb = r1l * SS_STRIDE;
                int tmax = t0 + r1l - s0;
                float mloc = -1e30f;
#pragma unroll
                for (int jj = 0; jj < 16; jj++) {
                    int cc = t4*16 + jj;
                    float v = Ss[rb + cc];
                    mloc = fmaxf(mloc, (cc <= tmax) ? v : -1e30f);
                }
                mloc = fmaxf(mloc, __shfl_xor_sync(0xffffffffu, mloc, 1));
                mloc = fmaxf(mloc, __shfl_xor_sync(0xffffffffu, mloc, 2));
                float mn = fmaxf(m1s, mloc);
                cf1 = __expf(m1s - mn);
                float ssum = 0.0f;
#pragma unroll
                for (int jj = 0; jj < 16; jj++) {
                    int cc = t4*16 + jj;
                    float v = Ss[rb + cc];
                    float e = (cc <= tmax) ? __expf(v - mn) : 0.0f;
                    Ss[rb + cc] = tfbits(e);
                    ssum += e;
                }
                ssum += __shfl_xor_sync(0xffffffffu, ssum, 1);
                ssum += __shfl_xor_sync(0xffffffffu, ssum, 2);
                l1s = l1s * cf1 + ssum;
                m1s = mn;
            }
#pragma unroll
            for (int nt = 0; nt < 4; nt++) {
                o[nt][0] *= cf0; o[nt][1] *= cf0;
                o[nt][2] *= cf1; o[nt][3] *= cf1;
            }
            __syncwarp();

            // ---- PV: O[16,32] += P[16,64] * V[64,32] ----
#pragma unroll
            for (int ks = 0; ks < 8; ks++) {
                uint32_t a0 = __float_as_uint(Ss[r0l * SS_STRIDE + ks*8 + t4]);
                uint32_t a1 = __float_as_uint(Ss[r1l * SS_STRIDE + ks*8 + t4]);
                uint32_t a2 = __float_as_uint(Ss[r0l * SS_STRIDE + ks*8 + t4 + 4]);
                uint32_t a3 = __float_as_uint(Ss[r1l * SS_STRIDE + ks*8 + t4 + 4]);
#pragma unroll
                for (int nt = 0; nt < 4; nt++) {
                    float2 bp = *(const float2*)&Vt[(nt*8 + g) * VT_STRIDE + ks*8 + t4*2];
                    mma_tf32(o[nt], a0, a1, a2, a3,
                             __float_as_uint(bp.x), __float_as_uint(bp.y));
                }
            }
        }
    }

    // ---- epilogue ----
    float inv0 = 1.0f / l0s, inv1 = 1.0f / l1s;
    float* p0 = &g_O[((size_t)b * TLEN + t0 + r0l) * NEMB + h * HDIM];
    float* p1 = &g_O[((size_t)b * TLEN + t0 + r1l) * NEMB + h * HDIM];
#pragma unroll
    for (int nt = 0; nt < 4; nt++) {
        int col = nt*8 + 2*t4;
        p0[col]     = o[nt][0] * inv0;
        p0[col + 1] = o[nt][1] * inv0;
        p1[col]     = o[nt][2] * inv1;
        p1[col + 1] = o[nt][3] * inv1;
    }
}

// ---------------------------------------------------------------------------
// Kernel 3: out = O @ w_proj + b_proj.
// ---------------------------------------------------------------------------
__global__ void proj_kernel(const float* __restrict__ w, const float* __restrict__ bias,
                            float* __restrict__ out) {
    __shared__ float As[64][20];
    __shared__ float Bs[16][68];
    int tid = threadIdx.x;
    int tx = tid & 15, ty = tid >> 4;
    int m0 = blockIdx.y * 64, n0 = blockIdx.x * 64;

    float acc[4][4] = {};

    for (int kk = 0; kk < 256; kk += 16) {
        {
            int row = tid >> 2, c4 = (tid & 3) * 4;
            float4 v = *(const float4*)&g_O[(size_t)(m0 + row) * 256 + kk + c4];
            As[row][c4] = v.x; As[row][c4+1] = v.y; As[row][c4+2] = v.z; As[row][c4+3] = v.w;
        }
        {
            int r = tid >> 4, c4 = (tid & 15) * 4;
            float4 v = *(const float4*)&w[(size_t)(kk + r) * 256 + n0 + c4];
            Bs[r][c4] = v.x; Bs[r][c4+1] = v.y; Bs[r][c4+2] = v.z; Bs[r][c4+3] = v.w;
        }
        __syncthreads();
#pragma unroll
        for (int k = 0; k < 16; k++) {
            float4 bv = *(const float4*)&Bs[k][tx * 4];
            float a0 = As[ty*4+0][k], a1 = As[ty*4+1][k], a2 = As[ty*4+2][k], a3 = As[ty*4+3][k];
            acc[0][0] += a0*bv.x; acc[0][1] += a0*bv.y; acc[0][2] += a0*bv.z; acc[0][3] += a0*bv.w;
            acc[1][0] += a1*bv.x; acc[1][1] += a1*bv.y; acc[1][2] += a1*bv.z; acc[1][3] += a1*bv.w;
            acc[2][0] += a2*bv.x; acc[2][1] += a2*bv.y; acc[2][2] += a2*bv.z; acc[2][3] += a2*bv.w;
            acc[3][0] += a3*bv.x; acc[3][1] += a3*bv.y; acc[3][2] += a3*bv.z; acc[3][3] += a3*bv.w;
        }
        __syncthreads();
    }

    int n = n0 + tx * 4;
    float b0 = bias[n], b1 = bias[n+1], b2 = bias[n+2], b3 = bias[n+3];
#pragma unroll
    for (int i = 0; i < 4; i++) {
        int m = m0 + ty * 4 + i;
        float* p = &out[(size_t)m * 256 + n];
        p[0] = acc[i][0] + b0; p[1] = acc[i][1] + b1;
        p[2] = acc[i][2] + b2; p[3] = acc[i][3] + b3;
    }
}

// ---------------------------------------------------------------------------
extern "C" void kernel_launch(void* const* d_in, const int* in_sizes, int n_in,
                              void* d_out, int out_size) {
    const float* x      = (const float*)d_in[0];
    const float* w_attn = (const float*)d_in[1];
    const float* pos    = (const float*)d_in[2];
    const float* w_proj = (const float*)d_in[3];
    const float* b_proj = (const float*)d_in[4];
    float* out = (float*)d_out;

    qkv_kernel<<<dim3(12, 128), 256>>>(x, w_attn);

    const size_t attn_smem =
        (64*KS_STRIDE + 32*VT_STRIDE + 192*PE_STRIDE + 128*SS_STRIDE) * sizeof(float); // 84992
    static int attr_set = 0;
    if (!attr_set) {
        cudaFuncSetAttribute(attn_kernel, cudaFuncAttributeMaxDynamicSharedMemorySize,
                             (int)attn_smem);
        attr_set = 1;
    }
    attn_kernel<<<dim3(16, 8, 4), 256, attn_smem>>>(pos);

    proj_kernel<<<dim3(4, 128), 256>>>(w_proj, b_proj, out);
}